// round 13
// baseline (speedup 1.0000x reference)
#include <cuda_runtime.h>
#include <cuda_bf16.h>
#include <math.h>
#include <stdint.h>

#define NB 32
#define NR 36
#define NL 40
#define ND 1024
#define NBB (NB*NB)
#define M_T2I (NBB*NL)
#define M_I2T (NBB*NR)
#define KW 4096          // [Xhi | Xlo], X = [q|wc]

// ---------------- scratch ---------------------------------------------------
__device__ __align__(128) float g_q   [M_T2I*ND];
__device__ __align__(128) float g_wc  [M_T2I*ND];
__device__ __align__(128) float g_tmp [M_T2I*2*ND];
__device__ __align__(128) __nv_bfloat16 g_xs[(size_t)M_T2I*KW];
__device__ __align__(128) __nv_bfloat16 g_ws[2][2048*2048];      // Whi only
__device__ float g_attn[NBB*NR*NL];
__device__ float g_capn[NB*NL];
__device__ float g_imgn[NB*NR];
__device__ int   g_dup [NBB];

// ---------------- helpers ---------------------------------------------------
__device__ __forceinline__ float warp_sum(float v){
    #pragma unroll
    for (int s = 16; s; s >>= 1) v += __shfl_xor_sync(0xffffffffu, v, s);
    return v;
}
__device__ __forceinline__ uint32_t smem_u32(const void* p){
    uint32_t a;
    asm("{ .reg .u64 t; cvta.to.shared.u64 t, %1; cvt.u32.u64 %0, t; }" : "=r"(a) : "l"(p));
    return a;
}
__device__ __forceinline__ void split2(float v, __nv_bfloat16& h, __nv_bfloat16& l){
    h = __float2bfloat16(v);
    l = __float2bfloat16(v - __bfloat162float(h));
}
__device__ __forceinline__ void cpa16(uint32_t dst, const void* src){
    asm volatile("cp.async.cg.shared.global [%0], [%1], 16;" :: "r"(dst), "l"(src) : "memory");
}
__device__ __forceinline__ void mma16816(float* c, const uint32_t* a, const uint32_t* b){
    asm volatile(
        "mma.sync.aligned.m16n8k16.row.col.f32.bf16.bf16.f32 "
        "{%0,%1,%2,%3}, {%4,%5,%6,%7}, {%8,%9}, {%0,%1,%2,%3};"
        : "+f"(c[0]), "+f"(c[1]), "+f"(c[2]), "+f"(c[3])
        : "r"(a[0]), "r"(a[1]), "r"(a[2]), "r"(a[3]), "r"(b[0]), "r"(b[1]));
}
__device__ __forceinline__ void ldsm4(uint32_t* d, uint32_t addr){
    asm volatile("ldmatrix.sync.aligned.m8n8.x4.shared.b16 {%0,%1,%2,%3}, [%4];"
        : "=r"(d[0]), "=r"(d[1]), "=r"(d[2]), "=r"(d[3]) : "r"(addr));
}

// ---------------- small kernels ---------------------------------------------
__global__ void k_zero_out(float* out){
    int i = blockIdx.x * blockDim.x + threadIdx.x;
    if (i < NBB) out[i] = 0.f;
}

__global__ void k_dup(const float* __restrict__ cap){
    int a = blockIdx.x / NB, b = blockIdx.x % NB;
    float s = 0.f;
    if (a != b){
        const float* pa = cap + (size_t)a * NL * ND;
        const float* pb = cap + (size_t)b * NL * ND;
        for (int idx = threadIdx.x; idx < NL*ND; idx += blockDim.x){
            float d = pa[idx] - pb[idx]; s += d * d;
        }
    }
    __shared__ float red[8];
    s = warp_sum(s);
    int lane = threadIdx.x & 31, wp = threadIdx.x >> 5;
    if (lane == 0) red[wp] = s;
    __syncthreads();
    if (threadIdx.x == 0){
        float t = 0.f;
        #pragma unroll
        for (int w = 0; w < 8; w++) t += red[w];
        g_dup[blockIdx.x] = (a != b) && (t <= 1e-6f);
    }
}

template<bool CAP>
__global__ void k_rownorm(const float* __restrict__ src){
    const float* p = src + (size_t)blockIdx.x * ND;
    float s = 0.f;
    for (int d = threadIdx.x; d < ND; d += blockDim.x){ float v = p[d]; s += v*v; }
    __shared__ float red[8];
    s = warp_sum(s);
    int lane = threadIdx.x & 31, wp = threadIdx.x >> 5;
    if (lane == 0) red[wp] = s;
    __syncthreads();
    if (threadIdx.x == 0){
        float t = 0.f;
        #pragma unroll
        for (int w = 0; w < 8; w++) t += red[w];
        if (CAP) g_capn[blockIdx.x] = sqrtf(t);
        else     g_imgn[blockIdx.x] = sqrtf(t);
    }
}

template<bool T2I>
__global__ void k_init_q(const float* __restrict__ src){
    int bid = blockIdx.x;
    int NQ = T2I ? NL : NR;
    int r = bid % NQ; int ci = bid / NQ;
    int own = T2I ? (ci / NB) : (ci % NB);
    const float* s = src + ((size_t)own * NQ + r) * ND;
    float* q = g_q + (size_t)bid * ND;
    __nv_bfloat16* xs = g_xs + (size_t)bid * KW;
    for (int d = threadIdx.x; d < ND; d += blockDim.x){
        float v = s[d];
        q[d] = v;
        __nv_bfloat16 h, l; split2(v, h, l);
        xs[d] = h; xs[2048 + d] = l;
    }
}

// ---------------- attn GEMM -------------------------------------------------
template<int NS, int NQ, int TS, int TQ, bool T2I>
__global__ void k_attn_gemm(const float* __restrict__ img, const float* __restrict__ cap){
    constexpr int NSG = NS / TS, NQG = NQ / TQ;
    int c = blockIdx.x / NB, i = blockIdx.x % NB;
    const float* S = T2I ? img + (size_t)i * NS * ND : cap + (size_t)c * NS * ND;
    const float* Q = g_q + (size_t)blockIdx.x * NQ * ND;
    __shared__ float sS[NS][33];
    __shared__ float sQ[NQ][33];
    int tid = threadIdx.x;
    int sg = tid / NQG, qg = tid % NQG;
    bool act = tid < NSG * NQG;
    float acc[TS][TQ];
    #pragma unroll
    for (int a = 0; a < TS; a++)
        #pragma unroll
        for (int b = 0; b < TQ; b++) acc[a][b] = 0.f;
    for (int k0 = 0; k0 < ND; k0 += 32){
        for (int idx = tid; idx < NS*32; idx += blockDim.x){
            int r = idx >> 5, cc = idx & 31;
            sS[r][cc] = S[(size_t)r * ND + k0 + cc];
        }
        for (int idx = tid; idx < NQ*32; idx += blockDim.x){
            int r = idx >> 5, cc = idx & 31;
            sQ[r][cc] = Q[(size_t)r * ND + k0 + cc];
        }
        __syncthreads();
        if (act){
            #pragma unroll
            for (int k = 0; k < 32; k++){
                float av[TS], bv[TQ];
                #pragma unroll
                for (int a = 0; a < TS; a++) av[a] = sS[sg*TS + a][k];
                #pragma unroll
                for (int b = 0; b < TQ; b++) bv[b] = sQ[qg*TQ + b][k];
                #pragma unroll
                for (int a = 0; a < TS; a++)
                    #pragma unroll
                    for (int b = 0; b < TQ; b++) acc[a][b] += av[a] * bv[b];
            }
        }
        __syncthreads();
    }
    if (act){
        float* A = g_attn + (size_t)blockIdx.x * NS * NQ;
        #pragma unroll
        for (int a = 0; a < TS; a++)
            #pragma unroll
            for (int b = 0; b < TQ; b++)
                A[(sg*TS + a) * NQ + qg*TQ + b] = acc[a][b];
    }
}

template<int NS, int NQ>
__global__ void k_attn_post(){
    __shared__ float t[NS*NQ];
    float* A = g_attn + (size_t)blockIdx.x * NS * NQ;
    int tid = threadIdx.x;
    for (int idx = tid; idx < NS*NQ; idx += blockDim.x){
        float v = A[idx];
        t[idx] = v > 0.f ? v : 0.1f * v;
    }
    __syncthreads();
    for (int s = tid; s < NS; s += blockDim.x){
        float sum = 0.f;
        for (int q = 0; q < NQ; q++){ float v = t[s*NQ + q]; sum += v*v; }
        float sc = 1.f / (sqrtf(sum) + 1e-8f);
        for (int q = 0; q < NQ; q++) t[s*NQ + q] *= sc;
    }
    __syncthreads();
    for (int q = tid; q < NQ; q += blockDim.x){
        float m = -1e30f;
        for (int s = 0; s < NS; s++) m = fmaxf(m, t[s*NQ + q]);
        float sum = 0.f;
        for (int s = 0; s < NS; s++){
            float e = expf(9.f * (t[s*NQ + q] - m));
            t[s*NQ + q] = e; sum += e;
        }
        float inv = 1.f / sum;
        for (int s = 0; s < NS; s++) t[s*NQ + q] *= inv;
    }
    __syncthreads();
    for (int idx = tid; idx < NS*NQ; idx += blockDim.x) A[idx] = t[idx];
}

template<int NS, int NQ, bool T2I>
__global__ void k_wc(const float* __restrict__ img, const float* __restrict__ cap){
    int c = blockIdx.x / NB, i = blockIdx.x % NB;
    const float* S = T2I ? img + (size_t)i * NS * ND : cap + (size_t)c * NS * ND;
    const float* A = g_attn + (size_t)blockIdx.x * NS * NQ;
    float* W = g_wc + (size_t)blockIdx.x * NQ * ND;
    __nv_bfloat16* xsb = g_xs + (size_t)blockIdx.x * NQ * KW;
    __shared__ float sAt[NQ][NS+1];
    __shared__ float sS[NS][64];
    int tid = threadIdx.x;
    for (int idx = tid; idx < NS*NQ; idx += blockDim.x){
        int s = idx / NQ, q = idx % NQ;
        sAt[q][s] = A[idx];
    }
    for (int d0 = 0; d0 < ND; d0 += 64){
        __syncthreads();
        for (int idx = tid; idx < NS*64; idx += blockDim.x){
            int s = idx >> 6, dd = idx & 63;
            sS[s][dd] = S[(size_t)s * ND + d0 + dd];
        }
        __syncthreads();
        int dd = tid & 63;
        int qb = tid >> 6;
        for (int pass = 0; pass < NQ/4; pass++){
            int q = pass*4 + qb;
            float acc = 0.f;
            #pragma unroll
            for (int s = 0; s < NS; s++) acc += sAt[q][s] * sS[s][dd];
            int d = d0 + dd;
            W[(size_t)q * ND + d] = acc;
            __nv_bfloat16 h, l; split2(acc, h, l);
            __nv_bfloat16* xr = xsb + (size_t)q * KW;
            xr[1024 + d] = h; xr[3072 + d] = l;
        }
    }
}

template<int NQ, bool T2I>
__global__ void k_sim(const float* __restrict__ img, const float* __restrict__ cap,
                      float* __restrict__ out){
    int c = blockIdx.x / NB, i = blockIdx.x % NB;
    const float* orig = T2I ? cap + (size_t)c * NQ * ND : img + (size_t)i * NQ * ND;
    const float* on   = T2I ? g_capn + c * NQ : g_imgn + i * NQ;
    const float* W = g_wc + (size_t)blockIdx.x * NQ * ND;
    int lane = threadIdx.x & 31, wp = threadIdx.x >> 5;
    float part = 0.f;
    for (int q = wp; q < NQ; q += 8){
        const float* o = orig + (size_t)q * ND;
        const float* w = W + (size_t)q * ND;
        float dot = 0.f, ns = 0.f;
        for (int d = lane; d < ND; d += 32){
            float wv = w[d];
            dot += o[d] * wv; ns += wv * wv;
        }
        dot = warp_sum(dot); ns = warp_sum(ns);
        if (lane == 0) part += dot / fmaxf(on[q] * sqrtf(ns), 1e-8f);
    }
    __shared__ float pr[8];
    if (lane == 0) pr[wp] = part;
    __syncthreads();
    if (threadIdx.x == 0){
        float s = 0.f;
        #pragma unroll
        for (int w2 = 0; w2 < 8; w2++) s += pr[w2];
        out[blockIdx.x] += g_dup[blockIdx.x] ? -1.0f : (s / (float)NQ);
    }
}

// ---------------- W' build: Whi only ----------------------------------------
__global__ void k_convert_w(int dir, const float* __restrict__ Wl, const float* __restrict__ Wg){
    int t = blockIdx.x * blockDim.x + threadIdx.x;
    if (t >= 2048*512) return;
    int n = t >> 9; int k = (t & 511) << 2;
    const float* src = (n < 1024) ? Wl + (size_t)n*2048 + k : Wg + (size_t)(n-1024)*2048 + k;
    float4 v = *(const float4*)src;
    __nv_bfloat16 h[4];
    h[0] = __float2bfloat16(v.x); h[1] = __float2bfloat16(v.y);
    h[2] = __float2bfloat16(v.z); h[3] = __float2bfloat16(v.w);
    *(uint2*)(g_ws[dir] + (size_t)n * 2048 + k) = *(uint2*)h;
}

// ---------------- GEMM: BM=128, BN=256, fused hi/lo, 512 thr ----------------
// tmp[m,n] = sum_k (Xhi[m,k]+Xlo[m,k]) * Whi[n,k] + bias(n)
#define GBK 32               // K per chunk (of Whi)
#define NKT (2048/GBK)       // 64
#define SROWB 80             // bytes per smem row (32 bf16 + 8 pad)
#define TILE_A (128*SROWB)       // 10240
#define TILE_B (256*SROWB)       // 20480
#define STG_BYTES (2*TILE_A + TILE_B)   // 40960
#define NSTG 3
#define GEMM_SMEM (NSTG*STG_BYTES)      // 122880

__global__ void __launch_bounds__(512, 1)
k_mma_gemm(int dir, const float* __restrict__ bl, const float* __restrict__ bgp){
    extern __shared__ __nv_bfloat16 sm[];
    uint32_t smb = smem_u32(sm);
    int tid = threadIdx.x, lane = tid & 31, wid = tid >> 5;
    int g = lane >> 2, tg = lane & 3;
    int wm = wid & 3, wn = wid >> 2;            // 4x4 warps: 32-row x 64-col tiles
    size_t m0 = (size_t)blockIdx.y * 128;
    int n0 = blockIdx.x * 256;

    float acc[2][8][4];
    #pragma unroll
    for (int mt = 0; mt < 2; mt++)
        #pragma unroll
        for (int nt = 0; nt < 8; nt++)
            #pragma unroll
            for (int j = 0; j < 4; j++) acc[mt][nt][j] = 0.f;

    const __nv_bfloat16* Abase = g_xs + m0 * KW;
    const __nv_bfloat16* Bbase = g_ws[dir] + (size_t)n0 * 2048;

    // cp.async: 2048 16B-chunks/stage, 4 per thread.
    // c<512: A-hi; c<1024: A-lo; else B. row=cc>>2, col16=cc&3.
    auto issue = [&](int kt){
        uint32_t sg0 = smb + (kt % NSTG) * STG_BYTES;
        int kof = kt * GBK;
        #pragma unroll
        for (int j = 0; j < 4; j++){
            int c = tid + j*512;
            if (c < 1024){
                int hi = c < 512;
                int cc = c & 511;
                int row = cc >> 2, col = cc & 3;
                const __nv_bfloat16* src = Abase + (size_t)row*KW + (hi ? 0 : 2048) + kof + col*8;
                cpa16(sg0 + (hi ? 0 : TILE_A) + row*SROWB + col*16, src);
            } else {
                int cc = c - 1024;
                int row = cc >> 2, col = cc & 3;
                cpa16(sg0 + 2*TILE_A + row*SROWB + col*16,
                      Bbase + (size_t)row*2048 + kof + col*8);
            }
        }
        asm volatile("cp.async.commit_group;" ::: "memory");
    };

    issue(0); issue(1);

    int lr16 = lane & 15;
    int lch  = (lane >> 4) * 8;

    for (int kt = 0; kt < NKT; kt++){
        asm volatile("cp.async.wait_group 1;" ::: "memory");
        __syncthreads();
        if (kt + 2 < NKT) issue(kt + 2);
        else asm volatile("cp.async.commit_group;" ::: "memory");

        uint32_t sg0 = smb + (kt % NSTG) * STG_BYTES;
        uint32_t sa_hi = sg0, sa_lo = sg0 + TILE_A, sb = sg0 + 2*TILE_A;
        #pragma unroll
        for (int ks = 0; ks < 2; ks++){
            int kk = ks * 16;
            uint32_t ah[2][4], al[2][4], bfr[8][2];
            #pragma unroll
            for (int mt = 0; mt < 2; mt++){
                int r = wm*32 + mt*16 + lr16;
                ldsm4(ah[mt], sa_hi + r*SROWB + (kk + lch)*2);
                ldsm4(al[mt], sa_lo + r*SROWB + (kk + lch)*2);
            }
            #pragma unroll
            for (int np = 0; np < 4; np++){
                uint32_t d[4];
                int r = wn*64 + np*16 + lr16;
                ldsm4(d, sb + r*SROWB + (kk + lch)*2);
                bfr[np*2][0] = d[0]; bfr[np*2+1][0] = d[1];
                bfr[np*2][1] = d[2]; bfr[np*2+1][1] = d[3];
            }
            #pragma unroll
            for (int mt = 0; mt < 2; mt++)
                #pragma unroll
                for (int nt = 0; nt < 8; nt++){
                    mma16816(acc[mt][nt], ah[mt], bfr[nt]);
                    mma16816(acc[mt][nt], al[mt], bfr[nt]);
                }
        }
    }

    #pragma unroll
    for (int nt = 0; nt < 8; nt++){
        int col = n0 + wn*64 + nt*8 + tg*2;
        float b0 = (col < 1024) ? bl[col] : bgp[col - 1024];
        float b1 = (col + 1 < 1024) ? bl[col + 1] : bgp[col + 1 - 1024];
        #pragma unroll
        for (int mt = 0; mt < 2; mt++){
            size_t row = m0 + wm*32 + mt*16 + g;
            g_tmp[row*2048 + col]     = acc[mt][nt][0] + b0;
            g_tmp[row*2048 + col + 1] = acc[mt][nt][1] + b1;
            g_tmp[(row+8)*2048 + col]     = acc[mt][nt][2] + b0;
            g_tmp[(row+8)*2048 + col + 1] = acc[mt][nt][3] + b1;
        }
    }
}

// ---------------- combine + write X' q-part --------------------------------
__global__ void k_combine(){
    int m = blockIdx.x;
    __shared__ float buf[ND];
    __shared__ float red[8];
    __shared__ float s_scale;
    const float* lr = g_tmp + (size_t)m * 2048;
    const float* gr = lr + 1024;
    float* q = g_q + (size_t)m * ND;
    __nv_bfloat16* xs = g_xs + (size_t)m * KW;
    float ss = 0.f;
    for (int d = threadIdx.x; d < ND; d += blockDim.x){
        float g = 1.f / (1.f + expf(-gr[d]));
        float l = tanhf(lr[d]);
        float v = q[d] * g + l * (1.f - g);
        buf[d] = v; ss += v * v;
    }
    ss = warp_sum(ss);
    int lane = threadIdx.x & 31, wp = threadIdx.x >> 5;
    if (lane == 0) red[wp] = ss;
    __syncthreads();
    if (threadIdx.x == 0){
        float t = 0.f;
        #pragma unroll
        for (int w = 0; w < 8; w++) t += red[w];
        s_scale = 1.f / (sqrtf(t) + 1e-8f);
    }
    __syncthreads();
    float sc = s_scale;
    for (int d = threadIdx.x; d < ND; d += blockDim.x){
        float v = buf[d] * sc;
        q[d] = v;
        __nv_bfloat16 h, l2; split2(v, h, l2);
        xs[d] = h; xs[2048 + d] = l2;
    }
}

// ---------------- launcher --------------------------------------------------
extern "C" void kernel_launch(void* const* d_in, const int* in_sizes, int n_in,
                              void* d_out, int out_size){
    const float* img = (const float*)d_in[0];
    const float* cap = (const float*)d_in[1];
    const float* Wlt = (const float*)d_in[2];
    const float* blt = (const float*)d_in[3];
    const float* Wgt = (const float*)d_in[4];
    const float* bgt = (const float*)d_in[5];
    const float* Wli = (const float*)d_in[6];
    const float* bli = (const float*)d_in[7];
    const float* Wgi = (const float*)d_in[8];
    const float* bgi = (const float*)d_in[9];
    float* out = (float*)d_out;

    cudaFuncSetAttribute(k_mma_gemm, cudaFuncAttributeMaxDynamicSharedMemorySize, GEMM_SMEM);

    // ---- t2i step 0 (k_mma_gemm at launch index 5 for ncu) ----
    k_init_q<true><<<M_T2I, 256>>>(cap);                               // 0
    k_convert_w<<<4096, 256>>>(0, Wlt, Wgt);                           // 1
    k_attn_gemm<NR, NL, 3, 2, true><<<NBB, 256>>>(img, cap);           // 2
    k_attn_post<NR, NL><<<NBB, 256>>>();                               // 3
    k_wc<NR, NL, true><<<NBB, 256>>>(img, cap);                        // 4
    k_mma_gemm<<<dim3(8, M_T2I/128), 512, GEMM_SMEM>>>(0, blt, bgt);   // 5
    k_combine<<<M_T2I, 256>>>();                                       // 6
    k_zero_out<<<4, 256>>>(out);
    k_dup<<<NBB, 256>>>(cap);
    k_rownorm<true><<<NB*NL, 256>>>(cap);
    k_rownorm<false><<<NB*NR, 256>>>(img);
    k_sim<NL, true><<<NBB, 256>>>(img, cap, out);
    k_convert_w<<<4096, 256>>>(1, Wli, Wgi);

    // ---- t2i steps 1,2 ----
    for (int step = 1; step < 3; ++step){
        k_attn_gemm<NR, NL, 3, 2, true><<<NBB, 256>>>(img, cap);
        k_attn_post<NR, NL><<<NBB, 256>>>();
        k_wc<NR, NL, true><<<NBB, 256>>>(img, cap);
        k_sim<NL, true><<<NBB, 256>>>(img, cap, out);
        if (step < 2){
            k_mma_gemm<<<dim3(8, M_T2I/128), 512, GEMM_SMEM>>>(0, blt, bgt);
            k_combine<<<M_T2I, 256>>>();
        }
    }

    // ---- image-to-text ----
    k_init_q<false><<<M_I2T, 256>>>(img);
    for (int step = 0; step < 3; ++step){
        k_attn_gemm<NL, NR, 2, 3, false><<<NBB, 256>>>(img, cap);
        k_attn_post<NL, NR><<<NBB, 256>>>();
        k_wc<NL, NR, false><<<NBB, 256>>>(img, cap);
        k_sim<NR, false><<<NBB, 256>>>(img, cap, out);
        if (step < 2){
            k_mma_gemm<<<dim3(8, M_I2T/128), 512, GEMM_SMEM>>>(1, bli, bgi);
            k_combine<<<M_I2T, 256>>>();
        }
    }
}

// round 15
// speedup vs baseline: 1.5507x; 1.5507x over previous
#include <cuda_runtime.h>
#include <cuda_bf16.h>
#include <math.h>
#include <stdint.h>

#define NB 32
#define NR 36
#define NL 40
#define ND 1024
#define NBB (NB*NB)
#define M_T2I (NBB*NL)
#define M_I2T (NBB*NR)
#define KW 2048          // Xhi only, X = [q|wc]

// ---------------- scratch ---------------------------------------------------
__device__ __align__(128) float g_q   [M_T2I*ND];
__device__ __align__(128) float g_wc  [M_T2I*ND];
__device__ __align__(128) float g_tmp [M_T2I*2*ND];
__device__ __align__(128) __nv_bfloat16 g_xs[(size_t)M_T2I*KW];
__device__ __align__(128) __nv_bfloat16 g_ws[2][2048*2048];      // Whi
__device__ float g_attn[NBB*NR*NL];
__device__ float g_capn[NB*NL];
__device__ float g_imgn[NB*NR];
__device__ int   g_dup [NBB];

// ---------------- helpers ---------------------------------------------------
__device__ __forceinline__ float warp_sum(float v){
    #pragma unroll
    for (int s = 16; s; s >>= 1) v += __shfl_xor_sync(0xffffffffu, v, s);
    return v;
}
__device__ __forceinline__ uint32_t smem_u32(const void* p){
    uint32_t a;
    asm("{ .reg .u64 t; cvta.to.shared.u64 t, %1; cvt.u32.u64 %0, t; }" : "=r"(a) : "l"(p));
    return a;
}
__device__ __forceinline__ void cpa16(uint32_t dst, const void* src){
    asm volatile("cp.async.cg.shared.global [%0], [%1], 16;" :: "r"(dst), "l"(src) : "memory");
}
__device__ __forceinline__ void mma16816(float* c, const uint32_t* a, const uint32_t* b){
    asm volatile(
        "mma.sync.aligned.m16n8k16.row.col.f32.bf16.bf16.f32 "
        "{%0,%1,%2,%3}, {%4,%5,%6,%7}, {%8,%9}, {%0,%1,%2,%3};"
        : "+f"(c[0]), "+f"(c[1]), "+f"(c[2]), "+f"(c[3])
        : "r"(a[0]), "r"(a[1]), "r"(a[2]), "r"(a[3]), "r"(b[0]), "r"(b[1]));
}
__device__ __forceinline__ void ldsm4(uint32_t* d, uint32_t addr){
    asm volatile("ldmatrix.sync.aligned.m8n8.x4.shared.b16 {%0,%1,%2,%3}, [%4];"
        : "=r"(d[0]), "=r"(d[1]), "=r"(d[2]), "=r"(d[3]) : "r"(addr));
}

// ---------------- small kernels ---------------------------------------------
__global__ void k_zero_out(float* out){
    int i = blockIdx.x * blockDim.x + threadIdx.x;
    if (i < NBB) out[i] = 0.f;
}

__global__ void k_dup(const float* __restrict__ cap){
    int a = blockIdx.x / NB, b = blockIdx.x % NB;
    float s = 0.f;
    if (a != b){
        const float* pa = cap + (size_t)a * NL * ND;
        const float* pb = cap + (size_t)b * NL * ND;
        for (int idx = threadIdx.x; idx < NL*ND; idx += blockDim.x){
            float d = pa[idx] - pb[idx]; s += d * d;
        }
    }
    __shared__ float red[8];
    s = warp_sum(s);
    int lane = threadIdx.x & 31, wp = threadIdx.x >> 5;
    if (lane == 0) red[wp] = s;
    __syncthreads();
    if (threadIdx.x == 0){
        float t = 0.f;
        #pragma unroll
        for (int w = 0; w < 8; w++) t += red[w];
        g_dup[blockIdx.x] = (a != b) && (t <= 1e-6f);
    }
}

template<bool CAP>
__global__ void k_rownorm(const float* __restrict__ src){
    const float* p = src + (size_t)blockIdx.x * ND;
    float s = 0.f;
    for (int d = threadIdx.x; d < ND; d += blockDim.x){ float v = p[d]; s += v*v; }
    __shared__ float red[8];
    s = warp_sum(s);
    int lane = threadIdx.x & 31, wp = threadIdx.x >> 5;
    if (lane == 0) red[wp] = s;
    __syncthreads();
    if (threadIdx.x == 0){
        float t = 0.f;
        #pragma unroll
        for (int w = 0; w < 8; w++) t += red[w];
        if (CAP) g_capn[blockIdx.x] = sqrtf(t);
        else     g_imgn[blockIdx.x] = sqrtf(t);
    }
}

template<bool T2I>
__global__ void k_init_q(const float* __restrict__ src){
    int bid = blockIdx.x;
    int NQ = T2I ? NL : NR;
    int r = bid % NQ; int ci = bid / NQ;
    int own = T2I ? (ci / NB) : (ci % NB);
    const float* s = src + ((size_t)own * NQ + r) * ND;
    float* q = g_q + (size_t)bid * ND;
    __nv_bfloat16* xs = g_xs + (size_t)bid * KW;
    for (int d = threadIdx.x; d < ND; d += blockDim.x){
        float v = s[d];
        q[d] = v;
        xs[d] = __float2bfloat16(v);
    }
}

// ---------------- attn GEMM -------------------------------------------------
template<int NS, int NQ, int TS, int TQ, bool T2I>
__global__ void k_attn_gemm(const float* __restrict__ img, const float* __restrict__ cap){
    constexpr int NSG = NS / TS, NQG = NQ / TQ;
    int c = blockIdx.x / NB, i = blockIdx.x % NB;
    const float* S = T2I ? img + (size_t)i * NS * ND : cap + (size_t)c * NS * ND;
    const float* Q = g_q + (size_t)blockIdx.x * NQ * ND;
    __shared__ float sS[NS][33];
    __shared__ float sQ[NQ][33];
    int tid = threadIdx.x;
    int sg = tid / NQG, qg = tid % NQG;
    bool act = tid < NSG * NQG;
    float acc[TS][TQ];
    #pragma unroll
    for (int a = 0; a < TS; a++)
        #pragma unroll
        for (int b = 0; b < TQ; b++) acc[a][b] = 0.f;
    for (int k0 = 0; k0 < ND; k0 += 32){
        for (int idx = tid; idx < NS*32; idx += blockDim.x){
            int r = idx >> 5, cc = idx & 31;
            sS[r][cc] = S[(size_t)r * ND + k0 + cc];
        }
        for (int idx = tid; idx < NQ*32; idx += blockDim.x){
            int r = idx >> 5, cc = idx & 31;
            sQ[r][cc] = Q[(size_t)r * ND + k0 + cc];
        }
        __syncthreads();
        if (act){
            #pragma unroll
            for (int k = 0; k < 32; k++){
                float av[TS], bv[TQ];
                #pragma unroll
                for (int a = 0; a < TS; a++) av[a] = sS[sg*TS + a][k];
                #pragma unroll
                for (int b = 0; b < TQ; b++) bv[b] = sQ[qg*TQ + b][k];
                #pragma unroll
                for (int a = 0; a < TS; a++)
                    #pragma unroll
                    for (int b = 0; b < TQ; b++) acc[a][b] += av[a] * bv[b];
            }
        }
        __syncthreads();
    }
    if (act){
        float* A = g_attn + (size_t)blockIdx.x * NS * NQ;
        #pragma unroll
        for (int a = 0; a < TS; a++)
            #pragma unroll
            for (int b = 0; b < TQ; b++)
                A[(sg*TS + a) * NQ + qg*TQ + b] = acc[a][b];
    }
}

template<int NS, int NQ>
__global__ void k_attn_post(){
    __shared__ float t[NS*NQ];
    float* A = g_attn + (size_t)blockIdx.x * NS * NQ;
    int tid = threadIdx.x;
    for (int idx = tid; idx < NS*NQ; idx += blockDim.x){
        float v = A[idx];
        t[idx] = v > 0.f ? v : 0.1f * v;
    }
    __syncthreads();
    for (int s = tid; s < NS; s += blockDim.x){
        float sum = 0.f;
        for (int q = 0; q < NQ; q++){ float v = t[s*NQ + q]; sum += v*v; }
        float sc = 1.f / (sqrtf(sum) + 1e-8f);
        for (int q = 0; q < NQ; q++) t[s*NQ + q] *= sc;
    }
    __syncthreads();
    for (int q = tid; q < NQ; q += blockDim.x){
        float m = -1e30f;
        for (int s = 0; s < NS; s++) m = fmaxf(m, t[s*NQ + q]);
        float sum = 0.f;
        for (int s = 0; s < NS; s++){
            float e = expf(9.f * (t[s*NQ + q] - m));
            t[s*NQ + q] = e; sum += e;
        }
        float inv = 1.f / sum;
        for (int s = 0; s < NS; s++) t[s*NQ + q] *= inv;
    }
    __syncthreads();
    for (int idx = tid; idx < NS*NQ; idx += blockDim.x) A[idx] = t[idx];
}

template<int NS, int NQ, bool T2I>
__global__ void k_wc(const float* __restrict__ img, const float* __restrict__ cap){
    int c = blockIdx.x / NB, i = blockIdx.x % NB;
    const float* S = T2I ? img + (size_t)i * NS * ND : cap + (size_t)c * NS * ND;
    const float* A = g_attn + (size_t)blockIdx.x * NS * NQ;
    float* W = g_wc + (size_t)blockIdx.x * NQ * ND;
    __nv_bfloat16* xsb = g_xs + (size_t)blockIdx.x * NQ * KW;
    __shared__ float sAt[NQ][NS+1];
    __shared__ float sS[NS][64];
    int tid = threadIdx.x;
    for (int idx = tid; idx < NS*NQ; idx += blockDim.x){
        int s = idx / NQ, q = idx % NQ;
        sAt[q][s] = A[idx];
    }
    for (int d0 = 0; d0 < ND; d0 += 64){
        __syncthreads();
        for (int idx = tid; idx < NS*64; idx += blockDim.x){
            int s = idx >> 6, dd = idx & 63;
            sS[s][dd] = S[(size_t)s * ND + d0 + dd];
        }
        __syncthreads();
        int dd = tid & 63;
        int qb = tid >> 6;
        for (int pass = 0; pass < NQ/4; pass++){
            int q = pass*4 + qb;
            float acc = 0.f;
            #pragma unroll
            for (int s = 0; s < NS; s++) acc += sAt[q][s] * sS[s][dd];
            int d = d0 + dd;
            W[(size_t)q * ND + d] = acc;
            xsb[(size_t)q * KW + 1024 + d] = __float2bfloat16(acc);
        }
    }
}

template<int NQ, bool T2I>
__global__ void k_sim(const float* __restrict__ img, const float* __restrict__ cap,
                      float* __restrict__ out){
    int c = blockIdx.x / NB, i = blockIdx.x % NB;
    const float* orig = T2I ? cap + (size_t)c * NQ * ND : img + (size_t)i * NQ * ND;
    const float* on   = T2I ? g_capn + c * NQ : g_imgn + i * NQ;
    const float* W = g_wc + (size_t)blockIdx.x * NQ * ND;
    int lane = threadIdx.x & 31, wp = threadIdx.x >> 5;
    float part = 0.f;
    for (int q = wp; q < NQ; q += 8){
        const float* o = orig + (size_t)q * ND;
        const float* w = W + (size_t)q * ND;
        float dot = 0.f, ns = 0.f;
        for (int d = lane; d < ND; d += 32){
            float wv = w[d];
            dot += o[d] * wv; ns += wv * wv;
        }
        dot = warp_sum(dot); ns = warp_sum(ns);
        if (lane == 0) part += dot / fmaxf(on[q] * sqrtf(ns), 1e-8f);
    }
    __shared__ float pr[8];
    if (lane == 0) pr[wp] = part;
    __syncthreads();
    if (threadIdx.x == 0){
        float s = 0.f;
        #pragma unroll
        for (int w2 = 0; w2 < 8; w2++) s += pr[w2];
        out[blockIdx.x] += g_dup[blockIdx.x] ? -1.0f : (s / (float)NQ);
    }
}

// ---------------- W' build: Whi ---------------------------------------------
__global__ void k_convert_w(int dir, const float* __restrict__ Wl, const float* __restrict__ Wg){
    int t = blockIdx.x * blockDim.x + threadIdx.x;
    if (t >= 2048*512) return;
    int n = t >> 9; int k = (t & 511) << 2;
    const float* src = (n < 1024) ? Wl + (size_t)n*2048 + k : Wg + (size_t)(n-1024)*2048 + k;
    float4 v = *(const float4*)src;
    __nv_bfloat16 h[4];
    h[0] = __float2bfloat16(v.x); h[1] = __float2bfloat16(v.y);
    h[2] = __float2bfloat16(v.z); h[3] = __float2bfloat16(v.w);
    *(uint2*)(g_ws[dir] + (size_t)n * 2048 + k) = *(uint2*)h;
}

// ---------------- GEMM (R11 config, K=2048): ldmatrix + cp.async 3-stage ----
// tmp[m,n] = Xhi[m,:].Whi[n,:] + bias(n).  BM=BN=128, BK=64, 8 warps.
#define GBK 64
#define NKT (KW/GBK)          // 32
#define SROW 72
#define STG_BYTES (2*128*SROW*2)
#define NSTG 3
#define GEMM_SMEM (NSTG*STG_BYTES)

__global__ void __launch_bounds__(256, 2)
k_mma_gemm(int dir, const float* __restrict__ bl, const float* __restrict__ bgp){
    extern __shared__ __nv_bfloat16 sm[];
    uint32_t smb = smem_u32(sm);
    int tid = threadIdx.x, lane = tid & 31, wid = tid >> 5;
    int g = lane >> 2, tg = lane & 3;
    int wm = wid & 3, wn = wid >> 2;
    size_t m0 = (size_t)blockIdx.y * 128;
    int n0 = blockIdx.x * 128;

    float acc[2][8][4];
    #pragma unroll
    for (int mt = 0; mt < 2; mt++)
        #pragma unroll
        for (int nt = 0; nt < 8; nt++)
            #pragma unroll
            for (int j = 0; j < 4; j++) acc[mt][nt][j] = 0.f;

    const __nv_bfloat16* Abase = g_xs + m0 * KW;
    const __nv_bfloat16* Bbase = g_ws[dir] + (size_t)n0 * 2048;

    int crow[4], ccol[4];
    #pragma unroll
    for (int j = 0; j < 4; j++){
        int c = tid + j*256;
        crow[j] = c >> 3; ccol[j] = c & 7;
    }

    auto issue = [&](int kt){
        int s = kt % NSTG;
        uint32_t sa = smb + s * STG_BYTES;
        uint32_t sb = sa + 128*SROW*2;
        const __nv_bfloat16* A = Abase + kt * GBK;
        const __nv_bfloat16* B = Bbase + kt * GBK;
        #pragma unroll
        for (int j = 0; j < 4; j++){
            cpa16(sa + crow[j]*(SROW*2) + ccol[j]*16, A + (size_t)crow[j]*KW + ccol[j]*8);
            cpa16(sb + crow[j]*(SROW*2) + ccol[j]*16, B + (size_t)crow[j]*2048 + ccol[j]*8);
        }
        asm volatile("cp.async.commit_group;" ::: "memory");
    };

    issue(0); issue(1);

    int lr16 = lane & 15;
    int lch  = (lane >> 4) * 8;

    for (int kt = 0; kt < NKT; kt++){
        asm volatile("cp.async.wait_group 1;" ::: "memory");
        __syncthreads();
        if (kt + 2 < NKT) issue(kt + 2);
        else asm volatile("cp.async.commit_group;" ::: "memory");

        int s = kt % NSTG;
        uint32_t sa = smb + s * STG_BYTES;
        uint32_t sb = sa + 128*SROW*2;
        #pragma unroll
        for (int ks = 0; ks < 4; ks++){
            int kk = ks * 16;
            uint32_t af[2][4], bfr[8][2];
            #pragma unroll
            for (int mt = 0; mt < 2; mt++){
                int r = wm*32 + mt*16 + lr16;
                ldsm4(af[mt], sa + r*(SROW*2) + (kk + lch)*2);
            }
            #pragma unroll
            for (int np = 0; np < 4; np++){
                uint32_t d[4];
                int r = wn*64 + np*16 + lr16;
                ldsm4(d, sb + r*(SROW*2) + (kk + lch)*2);
                bfr[np*2][0] = d[0]; bfr[np*2+1][0] = d[1];
                bfr[np*2][1] = d[2]; bfr[np*2+1][1] = d[3];
            }
            #pragma unroll
            for (int mt = 0; mt < 2; mt++)
                #pragma unroll
                for (int nt = 0; nt < 8; nt++)
                    mma16816(acc[mt][nt], af[mt], bfr[nt]);
        }
    }

    #pragma unroll
    for (int nt = 0; nt < 8; nt++){
        int col = n0 + wn*64 + nt*8 + tg*2;
        float b0 = (col < 1024) ? bl[col] : bgp[col - 1024];
        float b1 = (col + 1 < 1024) ? bl[col + 1] : bgp[col + 1 - 1024];
        #pragma unroll
        for (int mt = 0; mt < 2; mt++){
            size_t row = m0 + wm*32 + mt*16 + g;
            g_tmp[row*2048 + col]     = acc[mt][nt][0] + b0;
            g_tmp[row*2048 + col + 1] = acc[mt][nt][1] + b1;
            g_tmp[(row+8)*2048 + col]     = acc[mt][nt][2] + b0;
            g_tmp[(row+8)*2048 + col + 1] = acc[mt][nt][3] + b1;
        }
    }
}

// ---------------- combine + write Xhi q-part --------------------------------
__global__ void k_combine(){
    int m = blockIdx.x;
    __shared__ float buf[ND];
    __shared__ float red[8];
    __shared__ float s_scale;
    const float* lr = g_tmp + (size_t)m * 2048;
    const float* gr = lr + 1024;
    float* q = g_q + (size_t)m * ND;
    __nv_bfloat16* xs = g_xs + (size_t)m * KW;
    float ss = 0.f;
    for (int d = threadIdx.x; d < ND; d += blockDim.x){
        float g = 1.f / (1.f + expf(-gr[d]));
        float l = tanhf(lr[d]);
        float v = q[d] * g + l * (1.f - g);
        buf[d] = v; ss += v * v;
    }
    ss = warp_sum(ss);
    int lane = threadIdx.x & 31, wp = threadIdx.x >> 5;
    if (lane == 0) red[wp] = ss;
    __syncthreads();
    if (threadIdx.x == 0){
        float t = 0.f;
        #pragma unroll
        for (int w = 0; w < 8; w++) t += red[w];
        s_scale = 1.f / (sqrtf(t) + 1e-8f);
    }
    __syncthreads();
    float sc = s_scale;
    for (int d = threadIdx.x; d < ND; d += blockDim.x){
        float v = buf[d] * sc;
        q[d] = v;
        xs[d] = __float2bfloat16(v);
    }
}

// ---------------- launcher --------------------------------------------------
extern "C" void kernel_launch(void* const* d_in, const int* in_sizes, int n_in,
                              void* d_out, int out_size){
    const float* img = (const float*)d_in[0];
    const float* cap = (const float*)d_in[1];
    const float* Wlt = (const float*)d_in[2];
    const float* blt = (const float*)d_in[3];
    const float* Wgt = (const float*)d_in[4];
    const float* bgt = (const float*)d_in[5];
    const float* Wli = (const float*)d_in[6];
    const float* bli = (const float*)d_in[7];
    const float* Wgi = (const float*)d_in[8];
    const float* bgi = (const float*)d_in[9];
    float* out = (float*)d_out;

    cudaFuncSetAttribute(k_mma_gemm, cudaFuncAttributeMaxDynamicSharedMemorySize, GEMM_SMEM);

    // ---- t2i step 0 ----
    k_init_q<true><<<M_T2I, 256>>>(cap);
    k_convert_w<<<4096, 256>>>(0, Wlt, Wgt);
    k_attn_gemm<NR, NL, 3, 2, true><<<NBB, 256>>>(img, cap);
    k_attn_post<NR, NL><<<NBB, 256>>>();
    k_wc<NR, NL, true><<<NBB, 256>>>(img, cap);
    k_mma_gemm<<<dim3(16, M_T2I/128), 256, GEMM_SMEM>>>(0, blt, bgt);
    k_combine<<<M_T2I, 256>>>();
    k_zero_out<<<4, 256>>>(out);
    k_dup<<<NBB, 256>>>(cap);
    k_rownorm<true><<<NB*NL, 256>>>(cap);
    k_rownorm<false><<<NB*NR, 256>>>(img);
    k_sim<NL, true><<<NBB, 256>>>(img, cap, out);
    k_convert_w<<<4096, 256>>>(1, Wli, Wgi);

    // ---- t2i steps 1,2 ----
    for (int step = 1; step < 3; ++step){
        k_attn_gemm<NR, NL, 3, 2, true><<<NBB, 256>>>(img, cap);
        k_attn_post<NR, NL><<<NBB, 256>>>();
        k_wc<NR, NL, true><<<NBB, 256>>>(img, cap);
        k_sim<NL, true><<<NBB, 256>>>(img, cap, out);
        if (step < 2){
            k_mma_gemm<<<dim3(16, M_T2I/128), 256, GEMM_SMEM>>>(0, blt, bgt);
            k_combine<<<M_T2I, 256>>>();
        }
    }

    // ---- image-to-text ----
    k_init_q<false><<<M_I2T, 256>>>(img);
    for (int step = 0; step < 3; ++step){
        k_attn_gemm<NL, NR, 2, 3, false><<<NBB, 256>>>(img, cap);
        k_attn_post<NL, NR><<<NBB, 256>>>();
        k_wc<NL, NR, false><<<NBB, 256>>>(img, cap);
        k_sim<NR, false><<<NBB, 256>>>(img, cap, out);
        if (step < 2){
            k_mma_gemm<<<dim3(16, M_I2T/128), 256, GEMM_SMEM>>>(1, bli, bgi);
            k_combine<<<M_I2T, 256>>>();
        }
    }
}